// round 4
// baseline (speedup 1.0000x reference)
#include <cuda_runtime.h>

#define H  512
#define MT 32          // points per block
#define NT 256         // threads per block

typedef unsigned long long ull;

// ---- packed fp32x2 helpers (sm_100+; ptxas never emits FFMA2 on its own) ----
__device__ __forceinline__ ull pack2s(float x){
    ull r; asm("mov.b64 %0, {%1, %1};" : "=l"(r) : "f"(x)); return r;
}
__device__ __forceinline__ float2 unpack2(ull v){
    float2 f; asm("mov.b64 {%0, %1}, %2;" : "=f"(f.x), "=f"(f.y) : "l"(v)); return f;
}
__device__ __forceinline__ void fma2(ull &d, ull a, ull b){
    asm("fma.rn.f32x2 %0, %1, %2, %0;" : "+l"(d) : "l"(a), "l"(b));
}

__device__ __forceinline__ void acc_zero(ull acc[8][4]){
#pragma unroll
    for (int r = 0; r < 8; ++r)
#pragma unroll
        for (int c = 0; c < 4; ++c) acc[r][c] = 0ull;
}

// GEMM micro-kernel: acc[8 rows][4 f32x2-col-pairs] += S[32xH] @ W[HxH]
// thread (trow 0..3, tcol 0..63): rows trow*8..+8, cols tcol*8..+8
// W streamed from global (L2-resident) as ulonglong2 (4 floats = 2 packed pairs).
// Prefetch DEPTH 2: per-k compute window is ~128 cyc (2 warps/SMSP interleaved),
// L2 latency is 234-262 cyc, so depth 1 would expose ~100+ cyc of
// long-scoreboard stall per k; depth 2 covers the full latency.
__device__ __forceinline__ void gemm_tile(const float* __restrict__ S,
                                          const float* __restrict__ W,
                                          ull acc[8][4], int trow, int tcol)
{
    const ulonglong2* __restrict__ W2 = reinterpret_cast<const ulonglong2*>(W);
    const int widx = tcol * 2;            // 128 ulonglong2 per W row
    const float* __restrict__ Sb = S + trow * 8 * H;

    ulonglong2 w0a = W2[widx];
    ulonglong2 w0b = W2[widx + 1];
    ulonglong2 w1a = W2[128 + widx];
    ulonglong2 w1b = W2[128 + widx + 1];
#pragma unroll 4
    for (int k = 0; k < H; ++k){
        const int kn = (k + 2 < H) ? (k + 2) : (H - 1);   // clamped, branch-free
        ulonglong2 wna = W2[kn * 128 + widx];
        ulonglong2 wnb = W2[kn * 128 + widx + 1];
        ull u2[8];
#pragma unroll
        for (int r = 0; r < 8; ++r) u2[r] = pack2s(Sb[r * H + k]);
#pragma unroll
        for (int r = 0; r < 8; ++r){
            fma2(acc[r][0], u2[r], w0a.x);
            fma2(acc[r][1], u2[r], w0a.y);
            fma2(acc[r][2], u2[r], w0b.x);
            fma2(acc[r][3], u2[r], w0b.y);
        }
        w0a = w1a; w0b = w1b;
        w1a = wna; w1b = wnb;
    }
}

extern "C" __global__ void __launch_bounds__(NT, 1)
fcblock_kernel(const float* __restrict__ coords,
               const float* __restrict__ Wu0,  const float* __restrict__ bu0,
               const float* __restrict__ Wu,   const float* __restrict__ bu,
               const float* __restrict__ Wzuu, const float* __restrict__ bzuu,
               const float* __restrict__ Wzzu, const float* __restrict__ Wzzu_last,
               const float* __restrict__ Wyuu0,const float* __restrict__ byuu0,
               const float* __restrict__ Wyuu, const float* __restrict__ byuu,
               const float* __restrict__ Wzyu, const float* __restrict__ Wzyu_last,
               const float* __restrict__ Wzu0, const float* __restrict__ bzu0,
               const float* __restrict__ Wzu,  const float* __restrict__ bzu,
               const float* __restrict__ Wzu_last, const float* __restrict__ bzu_last,
               const float* __restrict__ pp, const float* __restrict__ ppu,
               const float* __restrict__ ppzu,
               float* __restrict__ out, int Npts)
{
    extern __shared__ float smem[];
    float* su   = smem;                 // [MT*H]  activations u
    float* sz   = su + MT * H;          // [MT*H]  activations z (also holds zz)
    float* sc   = sz + MT * H;          // [MT*4]  raw coords
    float* sred = sc + MT * 4;          // [3*NT]  reduction scratch

    const int tid  = threadIdx.x;
    const int trow = tid >> 6;          // 0..3
    const int tcol = tid & 63;          // 0..63
    const int n0   = tcol * 8;
    const int m0   = blockIdx.x * MT;

    const float P   = 10.f * pp[0];
    const float PU  = 10.f * ppu[0];
    const float PZU = 10.f * ppzu[0];

    if (tid < MT * 4){
        const int gidx = m0 * 4 + tid;
        sc[tid] = (gidx < Npts * 4) ? coords[gidx] : 0.f;
    }
    __syncthreads();

    // ---------------- stage 0 (K = 3) ----------------
#pragma unroll
    for (int r = 0; r < 8; ++r){
        const int m = trow * 8 + r;
        const float a0 = sc[m*4+0], a1 = sc[m*4+1], a2 = sc[m*4+2], y = sc[m*4+3];
        const float s0 = a0*Wyuu0[0] + a1*Wyuu0[1] + a2*Wyuu0[2] + byuu0[0];
        const float ys = y * s0;
#pragma unroll
        for (int c = 0; c < 8; ++c){
            const int n = n0 + c;
            float zv = a0*Wzu0[n] + a1*Wzu0[H+n] + a2*Wzu0[2*H+n] + bzu0[n] + ys*Wzyu[n];
            float uv = a0*Wu0[n]  + a1*Wu0[H+n]  + a2*Wu0[2*H+n]  + bu0[n];
            sz[m*H + n] = fmaxf(P  * zv, 0.f);
            su[m*H + n] = fmaxf(PU * uv, 0.f);
        }
    }
    __syncthreads();

    // ---------------- stages 1..2 (full H outputs) ----------------
#pragma unroll 1
    for (int i = 1; i <= 2; ++i){
        const float* Wzuu_i = Wzuu + (i-1)*H*H;
        const float* bzuu_i = bzuu + (i-1)*H;
        const float* Wzzu_i = Wzzu + (i-1)*H*H;
        const float* Wzu_i  = Wzu  + (i-1)*H*H;
        const float* bzu_i  = bzu  + (i-1)*H;
        const float* Wu_i   = Wu   + (i-1)*H*H;
        const float* bu_i   = bu   + (i-1)*H;
        const float* Wyuu_i = Wyuu + (i-1)*H;
        const float  byuu_i = byuu[i-1];
        const float* Wzyu_i = Wzyu + i*H;      // stage i uses Wzyu[i]

        ull acc[8][4];

        // (a) gate = relu(PZU*(u@Wzuu + bzuu));  zz = z * gate  (in place in sz)
        acc_zero(acc);
        gemm_tile(su, Wzuu_i, acc, trow, tcol);
#pragma unroll
        for (int r = 0; r < 8; ++r){
            const int m = trow * 8 + r;
#pragma unroll
            for (int c = 0; c < 4; ++c){
                float2 v = unpack2(acc[r][c]);
                const int n = n0 + 2*c;
                const float g0 = fmaxf(PZU * (v.x + bzuu_i[n]),   0.f);
                const float g1 = fmaxf(PZU * (v.y + bzuu_i[n+1]), 0.f);
                sz[m*H + n]     *= g0;
                sz[m*H + n + 1] *= g1;
            }
        }
        // partial dot s[m] = u[m,:] . Wyuu_i   (8 segments of 64, stride-8 to dodge banks)
        {
            const int rrow = tid >> 3, rseg = tid & 7;
            float ps = 0.f;
#pragma unroll 8
            for (int j = 0; j < 64; ++j){
                const int k = rseg + 8*j;
                ps += su[rrow*H + k] * Wyuu_i[k];
            }
            sred[rseg * 32 + rrow] = ps;
        }
        __syncthreads();   // zz + s-partials visible

        // (b) znew = zz@Wzzu + u@Wzu  (+ bias + y-term)
        acc_zero(acc);
        gemm_tile(sz, Wzzu_i, acc, trow, tcol);
        gemm_tile(su, Wzu_i,  acc, trow, tcol);
        __syncthreads();   // every thread done reading zz before overwrite
#pragma unroll
        for (int r = 0; r < 8; ++r){
            const int m = trow * 8 + r;
            float smv = 0.f;
#pragma unroll
            for (int j = 0; j < 8; ++j) smv += sred[j * 32 + m];
            const float yy = sc[m*4+3] * (smv + byuu_i);
#pragma unroll
            for (int c = 0; c < 4; ++c){
                float2 v = unpack2(acc[r][c]);
                const int n = n0 + 2*c;
                const float z0 = v.x + bzu_i[n]   + yy * Wzyu_i[n];
                const float z1 = v.y + bzu_i[n+1] + yy * Wzyu_i[n+1];
                sz[m*H + n]     = fmaxf(P * z0, 0.f);
                sz[m*H + n + 1] = fmaxf(P * z1, 0.f);
            }
        }

        // (c) unew = relu(PU*(u@Wu + bu))
        acc_zero(acc);
        gemm_tile(su, Wu_i, acc, trow, tcol);
        __syncthreads();   // every thread done reading u before overwrite
#pragma unroll
        for (int r = 0; r < 8; ++r){
            const int m = trow * 8 + r;
#pragma unroll
            for (int c = 0; c < 4; ++c){
                float2 v = unpack2(acc[r][c]);
                const int n = n0 + 2*c;
                su[m*H + n]     = fmaxf(PU * (v.x + bu_i[n]),   0.f);
                su[m*H + n + 1] = fmaxf(PU * (v.y + bu_i[n+1]), 0.f);
            }
        }
        __syncthreads();
    }

    // ---------------- final stage (outputs scalar per point) ----------------
    {
        const float* Wzuu2 = Wzuu + 2*H*H;
        const float* bzuu2 = bzuu + 2*H;
        const float* Wyuu2 = Wyuu + 2*H;

        ull acc[8][4];
        acc_zero(acc);
        gemm_tile(su, Wzuu2, acc, trow, tcol);
#pragma unroll
        for (int r = 0; r < 8; ++r){
            const int m = trow * 8 + r;
#pragma unroll
            for (int c = 0; c < 4; ++c){
                float2 v = unpack2(acc[r][c]);
                const int n = n0 + 2*c;
                const float g0 = fmaxf(PZU * (v.x + bzuu2[n]),   0.f);
                const float g1 = fmaxf(PZU * (v.y + bzuu2[n+1]), 0.f);
                sz[m*H + n]     *= g0;
                sz[m*H + n + 1] *= g1;
            }
        }
        __syncthreads();

        // three K=512 dots per point: zz.Wzzu_last, u.Wzu_last, u.Wyuu2
        const int rrow = tid >> 3, rseg = tid & 7;
        float p1 = 0.f, p2 = 0.f, p3 = 0.f;
#pragma unroll 8
        for (int j = 0; j < 64; ++j){
            const int k = rseg + 8*j;
            const float uk = su[rrow*H + k];
            const float zk = sz[rrow*H + k];
            p1 += zk * Wzzu_last[k];
            p2 += uk * Wzu_last[k];
            p3 += uk * Wyuu2[k];
        }
        sred[tid]          = p1;
        sred[NT + tid]     = p2;
        sred[2*NT + tid]   = p3;
        __syncthreads();

        if (tid < MT && (m0 + tid) < Npts){
            float s1 = 0.f, s2 = 0.f, s3 = 0.f;
#pragma unroll
            for (int j = 0; j < 8; ++j){
                s1 += sred[tid*8 + j];
                s2 += sred[NT + tid*8 + j];
                s3 += sred[2*NT + tid*8 + j];
            }
            out[m0 + tid] = s1 + s2 + bzu_last[0]
                          + sc[tid*4+3] * (s3 + byuu[2]) * Wzyu_last[0];
        }
    }
}

extern "C" void kernel_launch(void* const* d_in, const int* in_sizes, int n_in,
                              void* d_out, int out_size)
{
    const float* coords    = (const float*)d_in[0];
    const float* Wu0       = (const float*)d_in[1];
    const float* bu0       = (const float*)d_in[2];
    const float* Wu        = (const float*)d_in[3];
    const float* bu        = (const float*)d_in[4];
    const float* Wzuu      = (const float*)d_in[5];
    const float* bzuu      = (const float*)d_in[6];
    const float* Wzzu      = (const float*)d_in[7];
    const float* Wzzu_last = (const float*)d_in[8];
    const float* Wyuu0     = (const float*)d_in[9];
    const float* byuu0     = (const float*)d_in[10];
    const float* Wyuu      = (const float*)d_in[11];
    const float* byuu      = (const float*)d_in[12];
    const float* Wzyu      = (const float*)d_in[13];
    const float* Wzyu_last = (const float*)d_in[14];
    const float* Wzu0      = (const float*)d_in[15];
    const float* bzu0      = (const float*)d_in[16];
    const float* Wzu       = (const float*)d_in[17];
    const float* bzu       = (const float*)d_in[18];
    const float* Wzu_last  = (const float*)d_in[19];
    const float* bzu_last  = (const float*)d_in[20];
    const float* pp        = (const float*)d_in[21];
    const float* ppu       = (const float*)d_in[22];
    const float* ppzu      = (const float*)d_in[23];
    float* out = (float*)d_out;

    const int N = in_sizes[0] / 4;          // coords is (N,4)
    const int grid = (N + MT - 1) / MT;
    const size_t smem_bytes = (size_t)(2*MT*H + MT*4 + 3*NT) * sizeof(float);

    cudaFuncSetAttribute(fcblock_kernel,
                         cudaFuncAttributeMaxDynamicSharedMemorySize,
                         (int)smem_bytes);

    fcblock_kernel<<<grid, NT, smem_bytes>>>(
        coords, Wu0, bu0, Wu, bu, Wzuu, bzuu, Wzzu, Wzzu_last,
        Wyuu0, byuu0, Wyuu, byuu, Wzyu, Wzyu_last,
        Wzu0, bzu0, Wzu, bzu, Wzu_last, bzu_last,
        pp, ppu, ppzu, out, N);
}

// round 5
// speedup vs baseline: 1.1661x; 1.1661x over previous
#include <cuda_runtime.h>

#define H    512
#define MT   32          // points per block
#define NT   512         // threads per block (16 warps)
#define SROW 36          // padded m-stride of transposed activation tiles

typedef unsigned long long ull;

// ---- packed fp32x2 helpers (sm_100+) ----
__device__ __forceinline__ ull pack2s(float x){
    ull r; asm("mov.b64 %0, {%1, %1};" : "=l"(r) : "f"(x)); return r;
}
__device__ __forceinline__ float2 unpack2(ull v){
    float2 f; asm("mov.b64 {%0, %1}, %2;" : "=f"(f.x), "=f"(f.y) : "l"(v)); return f;
}
__device__ __forceinline__ void fma2(ull &d, ull a, ull b){
    asm("fma.rn.f32x2 %0, %1, %2, %0;" : "+l"(d) : "l"(a), "l"(b));
}

__device__ __forceinline__ void acc_zero(ull acc[4][4]){
#pragma unroll
    for (int r = 0; r < 4; ++r)
#pragma unroll
        for (int c = 0; c < 4; ++c) acc[r][c] = 0ull;
}

// acc[4 row-pairs][4 cols] += S^T[32 x H] (stored [k][m], stride SROW) @ W[HxH]
// thread: rows mbase..mbase+7 (4 f32x2 pairs), cols n0..n0+3.
// S: 2 broadcast LDS.128 per k, values arrive pre-packed as row-pair f32x2.
// W: one float4 LDG per k, depth-2 prefetch (covers 234-262 cyc L2 latency
// against the ~128-cyc per-k fma window).
__device__ __forceinline__ void gemmT(const float* __restrict__ S,
                                      const float* __restrict__ W,
                                      ull acc[4][4], int mbase, int tcol)
{
    const float4* __restrict__ W4 = reinterpret_cast<const float4*>(W); // 128 per row
    float4 w0 = W4[tcol];
    float4 w1 = W4[128 + tcol];
#pragma unroll 4
    for (int k = 0; k < H; ++k){
        const int kn = (k + 2 < H) ? (k + 2) : (H - 1);
        float4 wn = W4[kn * 128 + tcol];
        const ulonglong2 sA = *reinterpret_cast<const ulonglong2*>(S + k*SROW + mbase);
        const ulonglong2 sB = *reinterpret_cast<const ulonglong2*>(S + k*SROW + mbase + 4);
        const ull wd0 = pack2s(w0.x);
        const ull wd1 = pack2s(w0.y);
        const ull wd2 = pack2s(w0.z);
        const ull wd3 = pack2s(w0.w);
        fma2(acc[0][0], sA.x, wd0); fma2(acc[1][0], sA.y, wd0);
        fma2(acc[2][0], sB.x, wd0); fma2(acc[3][0], sB.y, wd0);
        fma2(acc[0][1], sA.x, wd1); fma2(acc[1][1], sA.y, wd1);
        fma2(acc[2][1], sB.x, wd1); fma2(acc[3][1], sB.y, wd1);
        fma2(acc[0][2], sA.x, wd2); fma2(acc[1][2], sA.y, wd2);
        fma2(acc[2][2], sB.x, wd2); fma2(acc[3][2], sB.y, wd2);
        fma2(acc[0][3], sA.x, wd3); fma2(acc[1][3], sA.y, wd3);
        fma2(acc[2][3], sB.x, wd3); fma2(acc[3][3], sB.y, wd3);
        w0 = w1; w1 = wn;
    }
}

extern "C" __global__ void __launch_bounds__(NT, 1)
fcblock_kernel(const float* __restrict__ coords,
               const float* __restrict__ Wu0,  const float* __restrict__ bu0,
               const float* __restrict__ Wu,   const float* __restrict__ bu,
               const float* __restrict__ Wzuu, const float* __restrict__ bzuu,
               const float* __restrict__ Wzzu, const float* __restrict__ Wzzu_last,
               const float* __restrict__ Wyuu0,const float* __restrict__ byuu0,
               const float* __restrict__ Wyuu, const float* __restrict__ byuu,
               const float* __restrict__ Wzyu, const float* __restrict__ Wzyu_last,
               const float* __restrict__ Wzu0, const float* __restrict__ bzu0,
               const float* __restrict__ Wzu,  const float* __restrict__ bzu,
               const float* __restrict__ Wzu_last, const float* __restrict__ bzu_last,
               const float* __restrict__ pp, const float* __restrict__ ppu,
               const float* __restrict__ ppzu,
               float* __restrict__ out, int Npts)
{
    extern __shared__ float smem[];
    float* suT  = smem;                     // [H][SROW]  u, transposed
    float* szT  = suT + H * SROW;           // [H][SROW]  z / zz, transposed
    float* sc   = szT + H * SROW;           // [MT*4]     raw coords
    float* syy  = sc + MT * 4;              // [MT]       per-row y-term
    float* sred = syy + MT;                 // [3*NT]     reduction scratch

    const int tid   = threadIdx.x;
    const int trow  = tid >> 7;             // 0..3
    const int tcol  = tid & 127;            // 0..127
    const int mbase = trow * 8;
    const int n0    = tcol * 4;
    const int m0    = blockIdx.x * MT;

    const float P   = 10.f * pp[0];
    const float PU  = 10.f * ppu[0];
    const float PZU = 10.f * ppzu[0];

    if (tid < MT * 4){
        const int gidx = m0 * 4 + tid;
        sc[tid] = (gidx < Npts * 4) ? coords[gidx] : 0.f;
    }
    __syncthreads();

    // ---------------- stage 0 (K = 3), write transposed ----------------
#pragma unroll
    for (int c = 0; c < 4; ++c){
        const int n = n0 + c;
        const float wz0 = Wzu0[n], wz1 = Wzu0[H+n], wz2 = Wzu0[2*H+n];
        const float wu0v = Wu0[n], wu1v = Wu0[H+n], wu2v = Wu0[2*H+n];
        const float bz = bzu0[n], buv = bu0[n], wy = Wzyu[n];
#pragma unroll
        for (int r = 0; r < 8; ++r){
            const int m = mbase + r;
            const float a0 = sc[m*4+0], a1 = sc[m*4+1], a2 = sc[m*4+2], y = sc[m*4+3];
            const float s0 = a0*Wyuu0[0] + a1*Wyuu0[1] + a2*Wyuu0[2] + byuu0[0];
            const float ys = y * s0;
            const float zv = a0*wz0 + a1*wz1 + a2*wz2 + bz + ys*wy;
            const float uv = a0*wu0v + a1*wu1v + a2*wu2v + buv;
            szT[n*SROW + m] = fmaxf(P  * zv, 0.f);
            suT[n*SROW + m] = fmaxf(PU * uv, 0.f);
        }
    }
    __syncthreads();

    // ---------------- stages 1..2 ----------------
#pragma unroll 1
    for (int i = 1; i <= 2; ++i){
        const float* Wzuu_i = Wzuu + (i-1)*H*H;
        const float* bzuu_i = bzuu + (i-1)*H;
        const float* Wzzu_i = Wzzu + (i-1)*H*H;
        const float* Wzu_i  = Wzu  + (i-1)*H*H;
        const float* bzu_i  = bzu  + (i-1)*H;
        const float* Wu_i   = Wu   + (i-1)*H*H;
        const float* bu_i   = bu   + (i-1)*H;
        const float* Wyuu_i = Wyuu + (i-1)*H;
        const float  byuu_i = byuu[i-1];
        const float* Wzyu_i = Wzyu + i*H;

        ull acc[4][4];

        // (a) gate = relu(PZU*(u@Wzuu+bzuu)); zz = z*gate (in place in szT)
        acc_zero(acc);
        gemmT(suT, Wzuu_i, acc, mbase, tcol);
#pragma unroll
        for (int c = 0; c < 4; ++c){
            const int n = n0 + c;
            const float bz = bzuu_i[n];
            float* zrow = szT + n*SROW + mbase;
#pragma unroll
            for (int rp = 0; rp < 4; ++rp){
                float2 v = unpack2(acc[rp][c]);
                zrow[2*rp]   *= fmaxf(PZU * (v.x + bz), 0.f);
                zrow[2*rp+1] *= fmaxf(PZU * (v.y + bz), 0.f);
            }
        }
        // partial dot s[m] = u[m,:].Wyuu_i  (16 segments of 32 k)
        {
            const int rrow = tid >> 4, rseg = tid & 15;   // rrow 0..31, rseg 0..15
            float ps = 0.f;
#pragma unroll 8
            for (int j = 0; j < 32; ++j){
                const int k = rseg + 16*j;
                ps += suT[k*SROW + rrow] * Wyuu_i[k];
            }
            sred[rseg * 32 + rrow] = ps;
        }
        __syncthreads();          // zz + partials visible

        // warp 0 folds partials into per-row y-term
        if (tid < MT){
            float s = 0.f;
#pragma unroll
            for (int sgi = 0; sgi < 16; ++sgi) s += sred[sgi*32 + tid];
            syy[tid] = sc[tid*4+3] * (s + byuu_i);
        }

        // (b) znew = zz@Wzzu + u@Wzu (+bias + y-term)
        acc_zero(acc);
        gemmT(szT, Wzzu_i, acc, mbase, tcol);
        gemmT(suT, Wzu_i,  acc, mbase, tcol);
        __syncthreads();          // all zz reads done; syy visible
#pragma unroll
        for (int c = 0; c < 4; ++c){
            const int n = n0 + c;
            const float bz = bzu_i[n], wy = Wzyu_i[n];
            float* zrow = szT + n*SROW + mbase;
#pragma unroll
            for (int rp = 0; rp < 4; ++rp){
                float2 v = unpack2(acc[rp][c]);
                const int m = mbase + 2*rp;
                zrow[2*rp]   = fmaxf(P * (v.x + bz + syy[m]   * wy), 0.f);
                zrow[2*rp+1] = fmaxf(P * (v.y + bz + syy[m+1] * wy), 0.f);
            }
        }

        // (c) unew = relu(PU*(u@Wu+bu))
        acc_zero(acc);
        gemmT(suT, Wu_i, acc, mbase, tcol);
        __syncthreads();          // all u reads done
#pragma unroll
        for (int c = 0; c < 4; ++c){
            const int n = n0 + c;
            const float bv = bu_i[n];
            float* urow = suT + n*SROW + mbase;
#pragma unroll
            for (int rp = 0; rp < 4; ++rp){
                float2 v = unpack2(acc[rp][c]);
                urow[2*rp]   = fmaxf(PU * (v.x + bv), 0.f);
                urow[2*rp+1] = fmaxf(PU * (v.y + bv), 0.f);
            }
        }
        __syncthreads();
    }

    // ---------------- final stage ----------------
    {
        const float* Wzuu2 = Wzuu + 2*H*H;
        const float* bzuu2 = bzuu + 2*H;
        const float* Wyuu2 = Wyuu + 2*H;

        ull acc[4][4];
        acc_zero(acc);
        gemmT(suT, Wzuu2, acc, mbase, tcol);
#pragma unroll
        for (int c = 0; c < 4; ++c){
            const int n = n0 + c;
            const float bz = bzuu2[n];
            float* zrow = szT + n*SROW + mbase;
#pragma unroll
            for (int rp = 0; rp < 4; ++rp){
                float2 v = unpack2(acc[rp][c]);
                zrow[2*rp]   *= fmaxf(PZU * (v.x + bz), 0.f);
                zrow[2*rp+1] *= fmaxf(PZU * (v.y + bz), 0.f);
            }
        }
        __syncthreads();

        // three K=512 dots per point
        const int rrow = tid >> 4, rseg = tid & 15;
        float p1 = 0.f, p2 = 0.f, p3 = 0.f;
#pragma unroll 8
        for (int j = 0; j < 32; ++j){
            const int k = rseg + 16*j;
            const float uk = suT[k*SROW + rrow];
            const float zk = szT[k*SROW + rrow];
            p1 += zk * Wzzu_last[k];
            p2 += uk * Wzu_last[k];
            p3 += uk * Wyuu2[k];
        }
        const int ridx = rseg * 32 + rrow;
        sred[ridx]          = p1;
        sred[NT + ridx]     = p2;
        sred[2*NT + ridx]   = p3;
        __syncthreads();

        if (tid < MT && (m0 + tid) < Npts){
            float s1 = 0.f, s2 = 0.f, s3 = 0.f;
#pragma unroll
            for (int sgi = 0; sgi < 16; ++sgi){
                s1 += sred[sgi*32 + tid];
                s2 += sred[NT + sgi*32 + tid];
                s3 += sred[2*NT + sgi*32 + tid];
            }
            out[m0 + tid] = s1 + s2 + bzu_last[0]
                          + sc[tid*4+3] * (s3 + byuu[2]) * Wzyu_last[0];
        }
    }
}

extern "C" void kernel_launch(void* const* d_in, const int* in_sizes, int n_in,
                              void* d_out, int out_size)
{
    const float* coords    = (const float*)d_in[0];
    const float* Wu0       = (const float*)d_in[1];
    const float* bu0       = (const float*)d_in[2];
    const float* Wu        = (const float*)d_in[3];
    const float* bu        = (const float*)d_in[4];
    const float* Wzuu      = (const float*)d_in[5];
    const float* bzuu      = (const float*)d_in[6];
    const float* Wzzu      = (const float*)d_in[7];
    const float* Wzzu_last = (const float*)d_in[8];
    const float* Wyuu0     = (const float*)d_in[9];
    const float* byuu0     = (const float*)d_in[10];
    const float* Wyuu      = (const float*)d_in[11];
    const float* byuu      = (const float*)d_in[12];
    const float* Wzyu      = (const float*)d_in[13];
    const float* Wzyu_last = (const float*)d_in[14];
    const float* Wzu0      = (const float*)d_in[15];
    const float* bzu0      = (const float*)d_in[16];
    const float* Wzu       = (const float*)d_in[17];
    const float* bzu       = (const float*)d_in[18];
    const float* Wzu_last  = (const float*)d_in[19];
    const float* bzu_last  = (const float*)d_in[20];
    const float* pp        = (const float*)d_in[21];
    const float* ppu       = (const float*)d_in[22];
    const float* ppzu      = (const float*)d_in[23];
    float* out = (float*)d_out;

    const int N = in_sizes[0] / 4;          // coords is (N,4)
    const int grid = (N + MT - 1) / MT;
    const size_t smem_bytes = (size_t)(2*H*SROW + MT*4 + MT + 3*NT) * sizeof(float);

    cudaFuncSetAttribute(fcblock_kernel,
                         cudaFuncAttributeMaxDynamicSharedMemorySize,
                         (int)smem_bytes);

    fcblock_kernel<<<grid, NT, smem_bytes>>>(
        coords, Wu0, bu0, Wu, bu, Wzuu, bzuu, Wzzu, Wzzu_last,
        Wyuu0, byuu0, Wyuu, byuu, Wzyu, Wzyu_last,
        Wzu0, bzu0, Wzu, bzu, Wzu_last, bzu_last,
        pp, ppu, ppzu, out, N);
}